// round 6
// baseline (speedup 1.0000x reference)
#include <cuda_runtime.h>
#include <cstdint>

#define NEG (-1e30f)
#define YDIM 256
#define TP1 513
#define TLAST 512
#define NQ4 8404992          /* 513*65536/4 */
#define SCAN_SMEM 140032     /* 1KB vec + 4KB redf + 4KB redi + 130816B backtrack */

// ---------------- device globals (no allocations allowed) ----------------
__device__ float g_la[514 * 256];
__device__ float g_lb[514 * 256];
__device__ float g_vd[2][256];
__device__ __align__(16) unsigned char g_idx[511 * 256];
__device__ float g_logZ;

// ---------------- kernel 1: logM = sum_k w_k * f[k], with boundary masks ----
__global__ void k_logM(const float4* __restrict__ f4,
                       const float* __restrict__ w,
                       float4* __restrict__ out) {
    __shared__ float sw[4];
    if (threadIdx.x < 4) sw[threadIdx.x] = w[threadIdx.x];
    __syncthreads();
    int e = blockIdx.x * blockDim.x + threadIdx.x;
    if (e >= NQ4) return;
    float4 a = f4[e];
    float4 b = f4[e + NQ4];
    float4 c = f4[e + 2 * NQ4];
    float4 d = f4[e + 3 * NQ4];
    float4 r;
    r.x = fmaf(sw[3], d.x, fmaf(sw[2], c.x, fmaf(sw[1], b.x, sw[0] * a.x)));
    r.y = fmaf(sw[3], d.y, fmaf(sw[2], c.y, fmaf(sw[1], b.y, sw[0] * a.y)));
    r.z = fmaf(sw[3], d.z, fmaf(sw[2], c.z, fmaf(sw[1], b.z, sw[0] * a.z)));
    r.w = fmaf(sw[3], d.w, fmaf(sw[2], c.w, fmaf(sw[1], b.w, sw[0] * a.w)));
    int t  = e >> 14;          // float4-index / 16384 = matrix index
    int q  = e & 16383;
    int i  = q >> 6;
    int j4 = q & 63;
    if (t == 0 && i != 0) { r.x = NEG; r.y = NEG; r.z = NEG; r.w = NEG; }
    if (t == TLAST) {
        if (j4 != 0) { r.x = NEG; r.y = NEG; r.z = NEG; r.w = NEG; }
        else         { r.y = NEG; r.z = NEG; r.w = NEG; }
    }
    out[e] = r;
}

// ---------------- cluster barrier helpers ----------------
__device__ __forceinline__ void cluster_sync_all() {
    asm volatile("barrier.cluster.arrive.aligned;" ::: "memory");
    asm volatile("barrier.cluster.wait.aligned;" ::: "memory");
}

// ---------------- kernel 2: the three scans (alpha / beta / viterbi) -------
// grid = 24 CTAs, cluster dims (8,1,1): cluster 0 = alpha, 1 = beta, 2 = viterbi
__global__ void __cluster_dims__(8, 1, 1) __launch_bounds__(256, 1)
k_scan(const float* __restrict__ lM, float* __restrict__ path_out) {
    extern __shared__ unsigned char smem_raw[];
    float* s_vec  = reinterpret_cast<float*>(smem_raw);          // 256 floats
    float* s_redf = s_vec + 256;                                 // 1024 floats
    int*   s_redi = reinterpret_cast<int*>(s_redf + 1024);       // 1024 ints
    unsigned char* s_bt = reinterpret_cast<unsigned char*>(s_redi + 1024); // 130816 B

    const int tid   = threadIdx.x;
    const int role  = blockIdx.x >> 3;
    const int crank = blockIdx.x & 7;

    if (role == 0) {
        // ---------------- forward alpha scan ----------------
        const int jq = tid & 7;        // this thread's float4 column group
        const int ig = tid >> 3;       // i block: i = ig*8 + m
        const int jbase = crank * 32;
        s_vec[tid] = (tid == 0) ? 0.f : NEG;
        if (crank == 0) g_la[tid] = (tid == 0) ? 0.f : NEG;
        float c = 0.f;
        __syncthreads();

        for (int t = 0; t <= TLAST; ++t) {
            const float4* p = reinterpret_cast<const float4*>(lM + (size_t)t * 65536)
                              + (jbase >> 2) + jq;
            float ax = 0.f, ay = 0.f, az = 0.f, aw = 0.f;
#pragma unroll
            for (int m = 0; m < 8; ++m) {
                int i = ig * 8 + m;
                float4 v = p[(size_t)i * 64];
                float a = s_vec[i];
                ax += __expf(a + v.x);
                ay += __expf(a + v.y);
                az += __expf(a + v.z);
                aw += __expf(a + v.w);
            }
            int col = jq * 4;
            s_redf[ig * 32 + col + 0] = ax;
            s_redf[ig * 32 + col + 1] = ay;
            s_redf[ig * 32 + col + 2] = az;
            s_redf[ig * 32 + col + 3] = aw;
            __syncthreads();
            if (tid < 32) {
                float S = 0.f;
#pragma unroll
                for (int g = 0; g < 32; ++g) S += s_redf[g * 32 + tid];
                g_la[(t + 1) * 256 + jbase + tid] = c + logf(S);
            }
            cluster_sync_all();
            float r = g_la[(t + 1) * 256 + tid];
            float v = r;
#pragma unroll
            for (int off = 16; off; off >>= 1)
                v = fmaxf(v, __shfl_xor_sync(0xffffffffu, v, off));
            if ((tid & 31) == 0) s_redf[tid >> 5] = v;
            __syncthreads();
            float mx = s_redf[0];
#pragma unroll
            for (int wv = 1; wv < 8; ++wv) mx = fmaxf(mx, s_redf[wv]);
            c = mx;
            s_vec[tid] = r - mx;
            __syncthreads();
        }
        // logZ = logsumexp(log_alpha[T+1])
        if (crank == 0 && tid == 0) {
            float sum = 0.f;
            for (int j = 0; j < 256; ++j) sum += __expf(s_vec[j]);
            g_logZ = c + logf(sum);
        }
    } else if (role == 1) {
        // ---------------- backward beta scan ----------------
        const int jq = tid & 7;        // float4 chunk within row
        const int iloc = tid >> 3;     // local row 0..31
        const int ibase = crank * 32;
        s_vec[tid] = (tid == 0) ? 0.f : NEG;
        if (crank == 0) g_lb[513 * 256 + tid] = (tid == 0) ? 0.f : NEG;
        float c = 0.f;
        __syncthreads();

        for (int t = TLAST; t >= 0; --t) {
            const float4* p = reinterpret_cast<const float4*>(
                lM + (size_t)t * 65536 + (size_t)(ibase + iloc) * 256);
            float acc = 0.f;
#pragma unroll
            for (int m = 0; m < 8; ++m) {
                float4 v = p[jq + m * 8];
                const float4 b = *reinterpret_cast<const float4*>(s_vec + (jq + m * 8) * 4);
                acc += __expf(v.x + b.x);
                acc += __expf(v.y + b.y);
                acc += __expf(v.z + b.z);
                acc += __expf(v.w + b.w);
            }
            acc += __shfl_xor_sync(0xffffffffu, acc, 1);
            acc += __shfl_xor_sync(0xffffffffu, acc, 2);
            acc += __shfl_xor_sync(0xffffffffu, acc, 4);
            if (jq == 0) g_lb[t * 256 + ibase + iloc] = c + logf(acc);
            cluster_sync_all();
            float r = g_lb[t * 256 + tid];
            float v = r;
#pragma unroll
            for (int off = 16; off; off >>= 1)
                v = fmaxf(v, __shfl_xor_sync(0xffffffffu, v, off));
            if ((tid & 31) == 0) s_redf[tid >> 5] = v;
            __syncthreads();
            float mx = s_redf[0];
#pragma unroll
            for (int wv = 1; wv < 8; ++wv) mx = fmaxf(mx, s_redf[wv]);
            c = mx;
            s_vec[tid] = r - mx;
            __syncthreads();
        }
    } else {
        // ---------------- viterbi (max-plus) scan + backtrack ----------------
        const int jq = tid & 7;
        const int ig = tid >> 3;
        const int jbase = crank * 32;
        s_vec[tid] = lM[tid];          // delta0 = logM[0, 0, :]
        __syncthreads();

        for (int s = 1; s <= 511; ++s) {
            const float4* p = reinterpret_cast<const float4*>(lM + (size_t)s * 65536)
                              + (jbase >> 2) + jq;
            float bx = -__int_as_float(0x7f800000) /* -inf */, by = bx, bz = bx, bw = bx;
            int ixx = 0, ixy = 0, ixz = 0, ixw = 0;
#pragma unroll
            for (int m = 0; m < 8; ++m) {
                int i = ig * 8 + m;
                float4 v = p[(size_t)i * 64];
                float d = s_vec[i];
                float t0 = d + v.x; if (t0 > bx) { bx = t0; ixx = i; }
                float t1 = d + v.y; if (t1 > by) { by = t1; ixy = i; }
                float t2 = d + v.z; if (t2 > bz) { bz = t2; ixz = i; }
                float t3 = d + v.w; if (t3 > bw) { bw = t3; ixw = i; }
            }
            int col = jq * 4;
            s_redf[ig * 32 + col + 0] = bx; s_redi[ig * 32 + col + 0] = ixx;
            s_redf[ig * 32 + col + 1] = by; s_redi[ig * 32 + col + 1] = ixy;
            s_redf[ig * 32 + col + 2] = bz; s_redi[ig * 32 + col + 2] = ixz;
            s_redf[ig * 32 + col + 3] = bw; s_redi[ig * 32 + col + 3] = ixw;
            __syncthreads();
            if (tid < 32) {
                float bv = s_redf[tid];
                int bi = s_redi[tid];
#pragma unroll
                for (int g = 1; g < 32; ++g) {       // ascending i => first-max
                    float v = s_redf[g * 32 + tid];
                    if (v > bv) { bv = v; bi = s_redi[g * 32 + tid]; }
                }
                g_vd[s & 1][jbase + tid] = bv;
                g_idx[(s - 1) * 256 + jbase + tid] = (unsigned char)bi;
            }
            cluster_sync_all();
            s_vec[tid] = g_vd[s & 1][tid];
            __syncthreads();
        }
        // backtrack on cluster rank 0 (table copied to SMEM)
        if (crank == 0) {
            const uint32_t* src = reinterpret_cast<const uint32_t*>(g_idx);
            uint32_t* dst = reinterpret_cast<uint32_t*>(s_bt);
            for (int k = tid; k < (511 * 256) / 4; k += 256) dst[k] = src[k];
            __syncthreads();
            if (tid == 0) {
                float bv = s_vec[0];
                int li = 0;
                for (int j = 1; j < 256; ++j) {
                    float v = s_vec[j];
                    if (v > bv) { bv = v; li = j; }
                }
                path_out[511] = (float)li;
                int y = li;
                for (int s2 = 510; s2 >= 0; --s2) {
                    y = s_bt[s2 * 256 + y];
                    path_out[s2] = (float)y;
                }
            }
        }
    }
}

// ---------------- kernel 3: p12 = exp(la + logM + lb - logZ), in place -----
__global__ void k_p12(float4* __restrict__ m) {
    int e = blockIdx.x * blockDim.x + threadIdx.x;
    if (e >= NQ4) return;
    int t  = e >> 14;
    int q  = e & 16383;
    int i  = q >> 6;
    int j4 = q & 63;
    float4 v = m[e];
    float A = g_la[t * 256 + i] - g_logZ;
    const float4 B = *reinterpret_cast<const float4*>(&g_lb[(t + 1) * 256 + j4 * 4]);
    float4 r;
    r.x = __expf(A + v.x + B.x);
    r.y = __expf(A + v.y + B.y);
    r.z = __expf(A + v.z + B.z);
    r.w = __expf(A + v.w + B.w);
    m[e] = r;
}

// ---------------- launcher ----------------
extern "C" void kernel_launch(void* const* d_in, const int* in_sizes, int n_in,
                              void* d_out, int out_size) {
    const float* f = (const float*)d_in[0];
    const float* w = (const float*)d_in[1];
    float* out = (float*)d_out;

    cudaFuncSetAttribute(k_scan, cudaFuncAttributeMaxDynamicSharedMemorySize, SCAN_SMEM);

    const int nb = (NQ4 + 255) / 256;   // 32832
    k_logM<<<nb, 256>>>((const float4*)f, w, (float4*)out);
    k_scan<<<24, 256, SCAN_SMEM>>>(out, out + (out_size - 512));
    k_p12<<<nb, 256>>>((float4*)out);
}